// round 4
// baseline (speedup 1.0000x reference)
#include <cuda_runtime.h>
#include <cstdint>

// Sparse 3D conv via warp-level bf16 mma.sync (m16n8k16), fp32 emulated with
// a bf16 hi/lo split (3 MMA passes: hi*hi + hi*lo + lo*hi).
// R4: each warp owns an m32 x n64 tile (two m16 subtiles) so every B-fragment
// load is reused twice -> half the L1 wavefronts per output vs R3.

static constexpr int kMVox = 100000;
static constexpr int kKVol = 27;
static constexpr int kCIn  = 32;
static constexpr int kCOut = 64;
static constexpr int M_TILE = 128;     // 4 warps x 32 rows

// B fragments, fragment-order: [koff][nb][lane][8 words]
// words 0..3 = hi {ks0.b0, ks0.b1, ks1.b0, ks1.b1}, words 4..7 = lo same order
__device__ __align__(16) unsigned g_bfrag[kKVol * 8 * 32 * 8];

// split two floats into packed bf16x2 hi and lo (first float in low 16 bits)
__device__ __forceinline__ void split2(float x, float y, unsigned& hi, unsigned& lo) {
    asm("cvt.rn.bf16x2.f32 %0, %1, %2;" : "=r"(hi) : "f"(y), "f"(x));
    float hx = __uint_as_float(hi << 16);
    float hy = __uint_as_float(hi & 0xFFFF0000u);
    float lx = x - hx, ly = y - hy;
    asm("cvt.rn.bf16x2.f32 %0, %1, %2;" : "=r"(lo) : "f"(ly), "f"(lx));
}

__global__ void prep_kernel(const float* __restrict__ kw) {
    int koff = blockIdx.x, tid = threadIdx.x;       // 27 x 256
    int nb = tid >> 5, lane = tid & 31;
    int g = lane >> 2, t = lane & 3;
    int n = nb * 8 + g;
    const float* W = kw + koff * kCIn * kCOut;      // W[i][n]
    unsigned* dst = g_bfrag + ((size_t)(koff * 8 + nb) * 32 + lane) * 8;
#pragma unroll
    for (int s = 0; s < 4; ++s) {                   // s = kstep*2 + bhalf
        int k = 2 * t + 8 * s;
        float vx = W[k * kCOut + n];
        float vy = W[(k + 1) * kCOut + n];
        unsigned h, l;
        split2(vx, vy, h, l);
        dst[s] = h;
        dst[4 + s] = l;
    }
}

__device__ __forceinline__ void mma16816(float* d, const unsigned* a,
                                         unsigned b0, unsigned b1) {
    asm volatile(
        "mma.sync.aligned.m16n8k16.row.col.f32.bf16.bf16.f32 "
        "{%0,%1,%2,%3}, {%4,%5,%6,%7}, {%8,%9}, {%0,%1,%2,%3};"
        : "+f"(d[0]), "+f"(d[1]), "+f"(d[2]), "+f"(d[3])
        : "r"(a[0]), "r"(a[1]), "r"(a[2]), "r"(a[3]), "r"(b0), "r"(b1));
}

__global__ __launch_bounds__(128, 4)
void conv_hmma_kernel(const float* __restrict__ feats,
                      const int*   __restrict__ in_idx,
                      const int*   __restrict__ mask,
                      float*       __restrict__ out) {
    const int w = threadIdx.x >> 5, lane = threadIdx.x & 31;
    const int g = lane >> 2, t = lane & 3;
    const int mbase = blockIdx.x * M_TILE + w * 32;
    // subtile 0 rows: mbase+g (+0), mbase+g+8 ; subtile 1: +16
    const int mr[4] = { mbase + g, mbase + g + 8, mbase + g + 16, mbase + g + 24 };

    float acc0[8][4], acc1[8][4];
#pragma unroll
    for (int i = 0; i < 8; ++i)
#pragma unroll
        for (int j = 0; j < 4; ++j) { acc0[i][j] = 0.f; acc1[i][j] = 0.f; }

    for (int koff = 0; koff < kKVol; ++koff) {
        const size_t off = (size_t)koff * kMVox;
        int ii[4];
#pragma unroll
        for (int q = 0; q < 4; ++q) {
            ii[q] = -1;
            if (mr[q] < kMVox && mask[off + mr[q]]) ii[q] = in_idx[off + mr[q]];
        }

        // gather all 4 rows (2 subtiles x 2 frag-rows), convert to bf16 hi/lo.
        // frag layout per subtile: a[kstep*4 + half*2 + {rowA,rowB}]
        unsigned ah0[8], al0[8], ah1[8], al1[8];
        const float2* p0 = (const float2*)(feats + (size_t)(ii[0] < 0 ? 0 : ii[0]) * kCIn);
        const float2* p1 = (const float2*)(feats + (size_t)(ii[1] < 0 ? 0 : ii[1]) * kCIn);
        const float2* p2 = (const float2*)(feats + (size_t)(ii[2] < 0 ? 0 : ii[2]) * kCIn);
        const float2* p3 = (const float2*)(feats + (size_t)(ii[3] < 0 ? 0 : ii[3]) * kCIn);
#pragma unroll
        for (int s = 0; s < 4; ++s) {
            float2 q0 = (ii[0] >= 0) ? p0[t + 4 * s] : make_float2(0.f, 0.f);
            float2 q1 = (ii[1] >= 0) ? p1[t + 4 * s] : make_float2(0.f, 0.f);
            float2 q2 = (ii[2] >= 0) ? p2[t + 4 * s] : make_float2(0.f, 0.f);
            float2 q3 = (ii[3] >= 0) ? p3[t + 4 * s] : make_float2(0.f, 0.f);
            int base = (s >> 1) * 4 + (s & 1) * 2;
            split2(q0.x, q0.y, ah0[base], al0[base]);
            split2(q1.x, q1.y, ah0[base + 1], al0[base + 1]);
            split2(q2.x, q2.y, ah1[base], al1[base]);
            split2(q3.x, q3.y, ah1[base + 1], al1[base + 1]);
        }

#pragma unroll
        for (int nb = 0; nb < 8; ++nb) {
            const uint4* bp = (const uint4*)g_bfrag +
                              ((size_t)(koff * 8 + nb) * 32 + lane) * 2;
            uint4 bh = bp[0], bl = bp[1];
            mma16816(acc0[nb], ah0 + 0, bh.x, bh.y);
            mma16816(acc0[nb], ah0 + 4, bh.z, bh.w);
            mma16816(acc0[nb], ah0 + 0, bl.x, bl.y);
            mma16816(acc0[nb], ah0 + 4, bl.z, bl.w);
            mma16816(acc0[nb], al0 + 0, bh.x, bh.y);
            mma16816(acc0[nb], al0 + 4, bh.z, bh.w);
            mma16816(acc1[nb], ah1 + 0, bh.x, bh.y);
            mma16816(acc1[nb], ah1 + 4, bh.z, bh.w);
            mma16816(acc1[nb], ah1 + 0, bl.x, bl.y);
            mma16816(acc1[nb], ah1 + 4, bl.z, bl.w);
            mma16816(acc1[nb], al1 + 0, bh.x, bh.y);
            mma16816(acc1[nb], al1 + 4, bh.z, bh.w);
        }
    }

    // store: subtile d0,d1 -> row mr[0/2]; d2,d3 -> row mr[1/3]
#pragma unroll
    for (int nb = 0; nb < 8; ++nb) {
        int n = nb * 8 + 2 * t;
        if (mr[0] < kMVox)
            *(float2*)(out + (size_t)mr[0] * kCOut + n) = make_float2(acc0[nb][0], acc0[nb][1]);
        if (mr[1] < kMVox)
            *(float2*)(out + (size_t)mr[1] * kCOut + n) = make_float2(acc0[nb][2], acc0[nb][3]);
        if (mr[2] < kMVox)
            *(float2*)(out + (size_t)mr[2] * kCOut + n) = make_float2(acc1[nb][0], acc1[nb][1]);
        if (mr[3] < kMVox)
            *(float2*)(out + (size_t)mr[3] * kCOut + n) = make_float2(acc1[nb][2], acc1[nb][3]);
    }
}

extern "C" void kernel_launch(void* const* d_in, const int* in_sizes, int n_in,
                              void* d_out, int out_size) {
    const float* feats  = (const float*)d_in[0];
    const float* kernel = (const float*)d_in[1];
    const int*   in_idx = (const int*)d_in[2];
    const int*   maskp  = (const int*)d_in[3];
    float*       out    = (float*)d_out;
    (void)in_sizes; (void)n_in; (void)out_size;

    prep_kernel<<<kKVol, 256>>>(kernel);
    int grid = (kMVox + M_TILE - 1) / M_TILE;   // 782
    conv_hmma_kernel<<<grid, 128>>>(feats, in_idx, maskp, out);
}

// round 5
// speedup vs baseline: 1.3263x; 1.3263x over previous
#include <cuda_runtime.h>
#include <cstdint>

// Sparse 3D conv via warp-level bf16 mma.sync (m16n8k16), fp32 emulated with
// a bf16 hi/lo split (3 MMA passes: hi*hi + hi*lo + lo*hi).
// R5 = R3 tiling (warp = m16 x n64) + 1-deep software pipeline:
//   - mask/idx loaded independently (no dependent chain), prefetched 1 iter ahead
//   - feature-row loads for k+1 issued before the k MMA block
// so gather latency is hidden under ~48 HMMAs instead of exposed every iter.

static constexpr int kMVox = 100000;
static constexpr int kKVol = 27;
static constexpr int kCIn  = 32;
static constexpr int kCOut = 64;
static constexpr int M_TILE = 128;     // 8 warps x 16 rows

// B fragments, fragment-order: [koff][nb][lane][8 words]
// words 0..3 = hi {ks0.b0, ks0.b1, ks1.b0, ks1.b1}, words 4..7 = lo same order
__device__ __align__(16) unsigned g_bfrag[kKVol * 8 * 32 * 8];

// split two floats into packed bf16x2 hi and lo (first float in low 16 bits)
__device__ __forceinline__ void split2(float x, float y, unsigned& hi, unsigned& lo) {
    asm("cvt.rn.bf16x2.f32 %0, %1, %2;" : "=r"(hi) : "f"(y), "f"(x));
    float hx = __uint_as_float(hi << 16);
    float hy = __uint_as_float(hi & 0xFFFF0000u);
    float lx = x - hx, ly = y - hy;
    asm("cvt.rn.bf16x2.f32 %0, %1, %2;" : "=r"(lo) : "f"(ly), "f"(lx));
}

__global__ void prep_kernel(const float* __restrict__ kw) {
    int koff = blockIdx.x, tid = threadIdx.x;       // 27 x 256
    int nb = tid >> 5, lane = tid & 31;
    int g = lane >> 2, t = lane & 3;
    int n = nb * 8 + g;
    const float* W = kw + koff * kCIn * kCOut;      // W[i][n]
    unsigned* dst = g_bfrag + ((size_t)(koff * 8 + nb) * 32 + lane) * 8;
#pragma unroll
    for (int s = 0; s < 4; ++s) {                   // s = kstep*2 + bhalf
        int k = 2 * t + 8 * s;
        float vx = W[k * kCOut + n];
        float vy = W[(k + 1) * kCOut + n];
        unsigned h, l;
        split2(vx, vy, h, l);
        dst[s] = h;
        dst[4 + s] = l;
    }
}

__device__ __forceinline__ void mma16816(float* d, const unsigned* a,
                                         unsigned b0, unsigned b1) {
    asm volatile(
        "mma.sync.aligned.m16n8k16.row.col.f32.bf16.bf16.f32 "
        "{%0,%1,%2,%3}, {%4,%5,%6,%7}, {%8,%9}, {%0,%1,%2,%3};"
        : "+f"(d[0]), "+f"(d[1]), "+f"(d[2]), "+f"(d[3])
        : "r"(a[0]), "r"(a[1]), "r"(a[2]), "r"(a[3]), "r"(b0), "r"(b1));
}

__global__ __launch_bounds__(256, 2)
void conv_hmma_kernel(const float* __restrict__ feats,
                      const int*   __restrict__ in_idx,
                      const int*   __restrict__ mask,
                      float*       __restrict__ out) {
    const int w = threadIdx.x >> 5, lane = threadIdx.x & 31;
    const int g = lane >> 2, t = lane & 3;
    const int mbase = blockIdx.x * M_TILE + w * 16;
    const int mA = mbase + g;        // rows for a0/a2
    const int mB = mbase + g + 8;    // rows for a1/a3
    const bool vA = mA < kMVox, vB = mB < kMVox;

    float acc[8][4];
#pragma unroll
    for (int i = 0; i < 8; ++i)
#pragma unroll
        for (int j = 0; j < 4; ++j) acc[i][j] = 0.f;

    // --- pipeline prologue: idx[0] and rows[0], then idx[1] ---
    // mask & idx issued independently, selected after both land.
    int i0, i1;
    {
        int mk0 = vA ? mask[mA] : 0;
        int ix0 = vA ? in_idx[mA] : 0;
        int mk1 = vB ? mask[mB] : 0;
        int ix1 = vB ? in_idx[mB] : 0;
        i0 = mk0 ? ix0 : -1;
        i1 = mk1 ? ix1 : -1;
    }
    float2 r0[4], r1[4];
    {
        const float2* p0 = (const float2*)(feats + (size_t)(i0 < 0 ? 0 : i0) * kCIn);
        const float2* p1 = (const float2*)(feats + (size_t)(i1 < 0 ? 0 : i1) * kCIn);
#pragma unroll
        for (int s = 0; s < 4; ++s) {
            r0[s] = (i0 >= 0) ? p0[t + 4 * s] : make_float2(0.f, 0.f);
            r1[s] = (i1 >= 0) ? p1[t + 4 * s] : make_float2(0.f, 0.f);
        }
    }
    int n0, n1;   // idx for k+1 (in flight)
    {
        size_t off = (size_t)kMVox;
        int mk0 = vA ? mask[off + mA] : 0;
        int ix0 = vA ? in_idx[off + mA] : 0;
        int mk1 = vB ? mask[off + mB] : 0;
        int ix1 = vB ? in_idx[off + mB] : 0;
        n0 = mk0 ? ix0 : -1;
        n1 = mk1 ? ix1 : -1;
    }

#pragma unroll 1
    for (int koff = 0; koff < kKVol; ++koff) {
        // --- convert current rows to fragments (frees r0/r1) ---
        unsigned ah[8], al[8];
#pragma unroll
        for (int s = 0; s < 4; ++s) {
            unsigned h0, l0, h1, l1;
            split2(r0[s].x, r0[s].y, h0, l0);
            split2(r1[s].x, r1[s].y, h1, l1);
            int base = (s >> 1) * 4 + (s & 1) * 2;
            ah[base] = h0; ah[base + 1] = h1;
            al[base] = l0; al[base + 1] = l1;
        }

        // --- issue rows for k+1 (idx prefetched one iter ago) ---
        if (koff + 1 < kKVol) {
            const float2* p0 = (const float2*)(feats + (size_t)(n0 < 0 ? 0 : n0) * kCIn);
            const float2* p1 = (const float2*)(feats + (size_t)(n1 < 0 ? 0 : n1) * kCIn);
#pragma unroll
            for (int s = 0; s < 4; ++s) {
                r0[s] = (n0 >= 0) ? p0[t + 4 * s] : make_float2(0.f, 0.f);
                r1[s] = (n1 >= 0) ? p1[t + 4 * s] : make_float2(0.f, 0.f);
            }
        }

        // --- issue idx for k+2 ---
        if (koff + 2 < kKVol) {
            size_t off = (size_t)(koff + 2) * kMVox;
            int mk0 = vA ? mask[off + mA] : 0;
            int ix0 = vA ? in_idx[off + mA] : 0;
            int mk1 = vB ? mask[off + mB] : 0;
            int ix1 = vB ? in_idx[off + mB] : 0;
            n0 = mk0 ? ix0 : -1;
            n1 = mk1 ? ix1 : -1;
        }

        // --- MMA block for k (latency cover for the loads above) ---
#pragma unroll
        for (int nb = 0; nb < 8; ++nb) {
            const uint4* bp = (const uint4*)g_bfrag +
                              ((size_t)(koff * 8 + nb) * 32 + lane) * 2;
            uint4 bh = bp[0], bl = bp[1];
            mma16816(acc[nb], ah + 0, bh.x, bh.y);   // hi*hi ks0
            mma16816(acc[nb], ah + 4, bh.z, bh.w);   // hi*hi ks1
            mma16816(acc[nb], ah + 0, bl.x, bl.y);   // hi*lo ks0
            mma16816(acc[nb], ah + 4, bl.z, bl.w);   // hi*lo ks1
            mma16816(acc[nb], al + 0, bh.x, bh.y);   // lo*hi ks0
            mma16816(acc[nb], al + 4, bh.z, bh.w);   // lo*hi ks1
        }
    }

    // store: d0,d1 -> row mA cols 2t,2t+1 of n-block; d2,d3 -> row mB
#pragma unroll
    for (int nb = 0; nb < 8; ++nb) {
        int n = nb * 8 + 2 * t;
        if (vA)
            *(float2*)(out + (size_t)mA * kCOut + n) = make_float2(acc[nb][0], acc[nb][1]);
        if (vB)
            *(float2*)(out + (size_t)mB * kCOut + n) = make_float2(acc[nb][2], acc[nb][3]);
    }
}

extern "C" void kernel_launch(void* const* d_in, const int* in_sizes, int n_in,
                              void* d_out, int out_size) {
    const float* feats  = (const float*)d_in[0];
    const float* kernel = (const float*)d_in[1];
    const int*   in_idx = (const int*)d_in[2];
    const int*   maskp  = (const int*)d_in[3];
    float*       out    = (float*)d_out;
    (void)in_sizes; (void)n_in; (void)out_size;

    prep_kernel<<<kKVol, 256>>>(kernel);
    int grid = (kMVox + M_TILE - 1) / M_TILE;   // 782
    conv_hmma_kernel<<<grid, 256>>>(feats, in_idx, maskp, out);
}

// round 6
// speedup vs baseline: 2.6360x; 1.9875x over previous
#include <cuda_runtime.h>
#include <cstdint>

// Sparse 3D conv via warp-level fp16 mma.sync (m16n8k16), SINGLE pass.
// fp16 quantization of both operands gives norm rel_err ~1.5e-4 (<1e-3 budget).
// K-dimension is permuted (baked into B prep) so each lane's A-fragment
// channels are 32B-contiguous -> gather is 4x LDG.128 per lane, minimal
// L1 wavefronts. Warp tile m16 x n64, 1-deep idx/row software pipeline.

static constexpr int kMVox = 100000;
static constexpr int kKVol = 27;
static constexpr int kCIn  = 32;
static constexpr int kCOut = 64;
static constexpr int M_TILE = 128;     // 8 warps x 16 rows

// B fragments, fp16, fragment-order with K-permutation:
// [koff][nb][lane] -> uint4 {ks0.b0, ks0.b1, ks1.b0, ks1.b1}
// word j of lane(g,t) = f16x2( W[8t+2j][n], W[8t+2j+1][n] ), n = nb*8+g
__device__ __align__(16) uint4 g_bfrag[kKVol * 8 * 32];

__device__ __forceinline__ unsigned f16x2(float x, float y) {
    unsigned r;
    asm("cvt.rn.f16x2.f32 %0, %1, %2;" : "=r"(r) : "f"(y), "f"(x));  // x -> low half
    return r;
}

__global__ void prep_kernel(const float* __restrict__ kw) {
    int koff = blockIdx.x, tid = threadIdx.x;       // 27 x 256
    int nb = tid >> 5, lane = tid & 31;
    int g = lane >> 2, t = lane & 3;
    int n = nb * 8 + g;
    const float* W = kw + koff * kCIn * kCOut;      // W[i][n]
    uint4 v;
    v.x = f16x2(W[(8 * t + 0) * kCOut + n], W[(8 * t + 1) * kCOut + n]);
    v.y = f16x2(W[(8 * t + 2) * kCOut + n], W[(8 * t + 3) * kCOut + n]);
    v.z = f16x2(W[(8 * t + 4) * kCOut + n], W[(8 * t + 5) * kCOut + n]);
    v.w = f16x2(W[(8 * t + 6) * kCOut + n], W[(8 * t + 7) * kCOut + n]);
    g_bfrag[(koff * 8 + nb) * 32 + lane] = v;
}

__device__ __forceinline__ void mma16816(float* d, const unsigned* a,
                                         unsigned b0, unsigned b1) {
    asm volatile(
        "mma.sync.aligned.m16n8k16.row.col.f32.f16.f16.f32 "
        "{%0,%1,%2,%3}, {%4,%5,%6,%7}, {%8,%9}, {%0,%1,%2,%3};"
        : "+f"(d[0]), "+f"(d[1]), "+f"(d[2]), "+f"(d[3])
        : "r"(a[0]), "r"(a[1]), "r"(a[2]), "r"(a[3]), "r"(b0), "r"(b1));
}

__global__ __launch_bounds__(256, 3)
void conv_hmma_kernel(const float* __restrict__ feats,
                      const int*   __restrict__ in_idx,
                      const int*   __restrict__ mask,
                      float*       __restrict__ out) {
    const int w = threadIdx.x >> 5, lane = threadIdx.x & 31;
    const int g = lane >> 2, t = lane & 3;
    const int mbase = blockIdx.x * M_TILE + w * 16;
    const int mA = mbase + g;        // fragment rows g
    const int mB = mbase + g + 8;    // fragment rows g+8
    const bool vA = mA < kMVox, vB = mB < kMVox;

    float acc[8][4];
#pragma unroll
    for (int i = 0; i < 8; ++i)
#pragma unroll
        for (int j = 0; j < 4; ++j) acc[i][j] = 0.f;

    // --- prologue: idx[0], rows[0], idx[1] in flight ---
    int i0, i1;
    {
        int mk0 = vA ? mask[mA] : 0;
        int ix0 = vA ? in_idx[mA] : 0;
        int mk1 = vB ? mask[mB] : 0;
        int ix1 = vB ? in_idx[mB] : 0;
        i0 = mk0 ? ix0 : -1;
        i1 = mk1 ? ix1 : -1;
    }
    // raw rows: rA = row mA chunks {2t, 2t+1}, rB = row mB
    float4 rA0, rA1, rB0, rB1;
    {
        const float4* pA = (const float4*)(feats + (size_t)(i0 < 0 ? 0 : i0) * kCIn);
        const float4* pB = (const float4*)(feats + (size_t)(i1 < 0 ? 0 : i1) * kCIn);
        float4 z = make_float4(0.f, 0.f, 0.f, 0.f);
        rA0 = (i0 >= 0) ? pA[2 * t] : z;
        rA1 = (i0 >= 0) ? pA[2 * t + 1] : z;
        rB0 = (i1 >= 0) ? pB[2 * t] : z;
        rB1 = (i1 >= 0) ? pB[2 * t + 1] : z;
    }
    int n0, n1;
    {
        size_t off = (size_t)kMVox;
        int mk0 = vA ? mask[off + mA] : 0;
        int ix0 = vA ? in_idx[off + mA] : 0;
        int mk1 = vB ? mask[off + mB] : 0;
        int ix1 = vB ? in_idx[off + mB] : 0;
        n0 = mk0 ? ix0 : -1;
        n1 = mk1 ? ix1 : -1;
    }

#pragma unroll 1
    for (int koff = 0; koff < kKVol; ++koff) {
        // --- convert current raw rows to fragments ---
        // rA0 = orig ch pairs (4t, 4t+1) -> frag q = t (ks0.a0), t+4 (ks0.a2)
        // rA1 = pairs (4t+2, 4t+3)       -> frag q = t+8 (ks1.a0), t+12 (ks1.a2)
        unsigned ak0[4], ak1[4];
        ak0[0] = f16x2(rA0.x, rA0.y);   // ks0 a0 (row g)
        ak0[1] = f16x2(rB0.x, rB0.y);   // ks0 a1 (row g+8)
        ak0[2] = f16x2(rA0.z, rA0.w);   // ks0 a2 (row g)
        ak0[3] = f16x2(rB0.z, rB0.w);   // ks0 a3 (row g+8)
        ak1[0] = f16x2(rA1.x, rA1.y);   // ks1 a0
        ak1[1] = f16x2(rB1.x, rB1.y);   // ks1 a1
        ak1[2] = f16x2(rA1.z, rA1.w);   // ks1 a2
        ak1[3] = f16x2(rB1.z, rB1.w);   // ks1 a3

        // --- issue rows for k+1 (idx prefetched one iter ago) ---
        if (koff + 1 < kKVol) {
            const float4* pA = (const float4*)(feats + (size_t)(n0 < 0 ? 0 : n0) * kCIn);
            const float4* pB = (const float4*)(feats + (size_t)(n1 < 0 ? 0 : n1) * kCIn);
            float4 z = make_float4(0.f, 0.f, 0.f, 0.f);
            rA0 = (n0 >= 0) ? pA[2 * t] : z;
            rA1 = (n0 >= 0) ? pA[2 * t + 1] : z;
            rB0 = (n1 >= 0) ? pB[2 * t] : z;
            rB1 = (n1 >= 0) ? pB[2 * t + 1] : z;
        }
        // --- issue idx for k+2 ---
        if (koff + 2 < kKVol) {
            size_t off = (size_t)(koff + 2) * kMVox;
            int mk0 = vA ? mask[off + mA] : 0;
            int ix0 = vA ? in_idx[off + mA] : 0;
            int mk1 = vB ? mask[off + mB] : 0;
            int ix1 = vB ? in_idx[off + mB] : 0;
            n0 = mk0 ? ix0 : -1;
            n1 = mk1 ? ix1 : -1;
        }

        // --- MMA block: 8 n-blocks x 2 k-steps ---
        const uint4* bp = g_bfrag + (size_t)koff * 8 * 32 + lane;
#pragma unroll
        for (int nb = 0; nb < 8; ++nb) {
            uint4 bw = bp[nb * 32];
            mma16816(acc[nb], ak0, bw.x, bw.y);
            mma16816(acc[nb], ak1, bw.z, bw.w);
        }
    }

    // store: d0,d1 -> row mA cols nb*8+2t..+1 ; d2,d3 -> row mB
#pragma unroll
    for (int nb = 0; nb < 8; ++nb) {
        int n = nb * 8 + 2 * t;
        if (vA)
            *(float2*)(out + (size_t)mA * kCOut + n) = make_float2(acc[nb][0], acc[nb][1]);
        if (vB)
            *(float2*)(out + (size_t)mB * kCOut + n) = make_float2(acc[nb][2], acc[nb][3]);
    }
}

extern "C" void kernel_launch(void* const* d_in, const int* in_sizes, int n_in,
                              void* d_out, int out_size) {
    const float* feats  = (const float*)d_in[0];
    const float* kernel = (const float*)d_in[1];
    const int*   in_idx = (const int*)d_in[2];
    const int*   maskp  = (const int*)d_in[3];
    float*       out    = (float*)d_out;
    (void)in_sizes; (void)n_in; (void)out_size;

    prep_kernel<<<kKVol, 256>>>(kernel);
    int grid = (kMVox + M_TILE - 1) / M_TILE;   // 782
    conv_hmma_kernel<<<grid, 256>>>(feats, in_idx, maskp, out);
}